// round 15
// baseline (speedup 1.0000x reference)
#include <cuda_runtime.h>
#include <math.h>

#define T_LEN    176400
#define NBATCH   16
#define NHARM    64
#define NBANDS   65
#define MAIN_NB  690          // ceil(176400/256)
#define NORM_BPR 87           // 87*512 = 44544 >= 44100 float4 per row
#define PI_D 3.141592653589793115997963468544185161590576171875

// Scratch (no allocations allowed). Layout [batch][block]: norm's reduce
// reads are coalesced. Every slot overwritten by plain stores each call
// before being read -> no reset needed, replay-deterministic.
__device__ float g_partial[NBATCH * MAIN_NB];

// ---------------------------------------------------------------------------
// Range reduction, bit-exact w.r.t. the reference's f32 argument:
//  n = RNE(arg/2pi) via 1.5*2^23 magic; 2-term Cody-Waite -> r in [-pi,pi]
//  (4 fma-pipe ops, 3 with immediate operands), then __sinf(r) on MUFU.
// ---------------------------------------------------------------------------
__device__ __forceinline__ float sin_reduced(float a) {
    const float I2PI  = 0.15915494309189535f;
    const float MAGIC = 12582912.0f;                // 1.5 * 2^23
    const float C1    = 6.28318548202514648437500f; // fl32(2*pi)
    const float C2N   = 1.7484556000744625e-7f;     // -(2*pi - C1)
    float t  = fmaf(a, I2PI, MAGIC);
    float nf = t - MAGIC;                           // RNE(a/2pi), exact int
    float r  = fmaf(nf, -C1, a);
    r = fmaf(nf, C2N, r);                           // r in ~[-pi, pi]
    return __sinf(r);                               // MUFU pipe
}

// ---------------------------------------------------------------------------
// Main kernel: one thread = one time sample x ALL 16 batches (minimum total
// FMA-pipe instruction count: 248M vs 294M for the 8-batch split, and half
// the MUFU work). R14's validated fixes applied:
//  - noise tile staged to SHARED in the prologue (coalesced LDG; epilogue
//    reads are LDS — no exposed end-of-kernel DRAM latency, no +16 regs)
//  - per-batch max via REDUX.MAX
//  - parallel prologue: nbands sum by 16 lanes/batch + shfl tree (the old
//    single-thread 65-load serial chain stalled the whole block at the
//    first barrier)
// ---------------------------------------------------------------------------
__global__ void ddsp_main(
    const float* __restrict__ hd,      // (16, 64)
    const float* __restrict__ nbands,  // (16, 65)
    const float* __restrict__ adsr,    // (16, 4)
    const float* __restrict__ gain,    // (16, 1)
    const float* __restrict__ noise,   // (16, T)
    float* __restrict__ out)           // (16, T)
{
    __shared__ __align__(16) float sh_hd[NHARM * NBATCH];   // [k][b]
    __shared__ float sh_ck[NHARM];
    __shared__ float sh_noise[NBATCH * 256];                // [b][tid]
    __shared__ float sh_par[NBATCH * 12];
    __shared__ unsigned int sh_max[NBATCH];

    int tid = threadIdx.x;
    int i   = blockIdx.x * 256 + tid;
    bool act = (i < T_LEN);

    // harmonic weights, transposed [k][b]
    for (int idx = tid; idx < NHARM * NBATCH; idx += 256) {
        int k = idx >> 4, b = idx & 15;
        sh_hd[idx] = hd[b * NHARM + k];
    }
    if (tid < NHARM) {
        const float C32 = (float)(2.0 * PI_D * 440.0);   // fl32(2*pi*440)
        sh_ck[tid] = __fmul_rn(C32, (float)(tid + 1));   // bit-exact ref ck
    }
    // noise tile -> shared (coalesced rows; zero-fill past T_LEN)
    for (int idx = tid; idx < NBATCH * 256; idx += 256) {
        int b = idx >> 8, col = idx & 255;
        int ii = blockIdx.x * 256 + col;
        sh_noise[idx] = (ii < T_LEN) ? noise[b * T_LEN + ii] : 0.0f;
    }
    // nbands sum: 16 lanes per batch, strided, then 16-lane shfl tree
    {
        int b = tid >> 4, l = tid & 15;
        float ps = 0.0f;
        for (int j = l; j < NBANDS; j += 16) ps += nbands[b * NBANDS + j];
#pragma unroll
        for (int off = 8; off; off >>= 1)
            ps += __shfl_xor_sync(0xFFFFFFFFu, ps, off);
        if (l == 0) {
            sh_max[b] = 0u;
            float nl = (ps / (float)NBANDS) * 0.1f;

            float attack  = adsr[b * 4 + 0];
            float decay   = adsr[b * 4 + 1];
            float sus     = adsr[b * 4 + 2];
            float release = adsr[b * 4 + 3];

            int a  = (int)floorf(__fmul_rn(__fmul_rn(attack,  0.5f), 44100.0f)) + 1;
            int dd = (int)floorf(__fmul_rn(__fmul_rn(decay,   0.5f), 44100.0f)) + 1;
            int rr = (int)floorf(__fmul_rn(__fmul_rn(release, 0.5f), 44100.0f)) + 1;
            int total = a + dd + rr;
            if (total > T_LEN) {
                float scale = __fdiv_rn((float)T_LEN, (float)total);
                a  = (int)floorf(__fmul_rn((float)a,  scale));
                dd = (int)floorf(__fmul_rn((float)dd, scale));
                rr = (int)floorf(__fmul_rn((float)rr, scale));
            }
            int ss = T_LEN - (a + dd + rr);
            if (ss < 0) ss = 0;

            float af = (float)a, df = (float)dd, sf = (float)ss, rf = (float)rr;
            float* P = sh_par + b * 12;
            P[0] = af;
            P[1] = af + df;
            P[2] = af + df + sf;
            P[3] = 1.0f / fmaxf(af - 1.0f, 1.0f);
            P[4] = 1.0f / fmaxf(df - 1.0f, 1.0f);
            P[5] = 1.0f / fmaxf(rf - 1.0f, 1.0f);
            P[6] = sus;
            P[7] = gain[b];
            P[8] = nl;
        }
    }
    __syncthreads();

    float fi = (float)i;
    const float DELTA = 4.0f / 176399.0f;         // compile-time IEEE f32
    float ti = __fmul_rn(fi, DELTA);              // jax linspace: iota*delta

    float acc[NBATCH];
#pragma unroll
    for (int b = 0; b < NBATCH; b++) acc[b] = 0.0f;

#pragma unroll 8
    for (int k = 0; k < NHARM; k++) {
        float sv = sin_reduced(__fmul_rn(sh_ck[k], ti)); // ref f32 rounding
        const float4* hp = (const float4*)(sh_hd + k * NBATCH);
        float4 h0 = hp[0], h1 = hp[1], h2 = hp[2], h3 = hp[3];
        acc[0]  = fmaf(h0.x, sv, acc[0]);  acc[1]  = fmaf(h0.y, sv, acc[1]);
        acc[2]  = fmaf(h0.z, sv, acc[2]);  acc[3]  = fmaf(h0.w, sv, acc[3]);
        acc[4]  = fmaf(h1.x, sv, acc[4]);  acc[5]  = fmaf(h1.y, sv, acc[5]);
        acc[6]  = fmaf(h1.z, sv, acc[6]);  acc[7]  = fmaf(h1.w, sv, acc[7]);
        acc[8]  = fmaf(h2.x, sv, acc[8]);  acc[9]  = fmaf(h2.y, sv, acc[9]);
        acc[10] = fmaf(h2.z, sv, acc[10]); acc[11] = fmaf(h2.w, sv, acc[11]);
        acc[12] = fmaf(h3.x, sv, acc[12]); acc[13] = fmaf(h3.y, sv, acc[13]);
        acc[14] = fmaf(h3.z, sv, acc[14]); acc[15] = fmaf(h3.w, sv, acc[15]);
    }

#pragma unroll
    for (int b = 0; b < NBATCH; b++) {
        const float* P = sh_par + b * 12;
        float af = P[0], afd = P[1], ads = P[2];
        float ida = P[3], idd = P[4], idr = P[5];
        float sus = P[6], gn = P[7], nl = P[8];

        float env;
        if (fi < af)       env = fi * ida;
        else if (fi < afd) env = 1.0f + ((sus - 1.0f) * (fi - af)) * idd;
        else if (fi < ads) env = sus;
        else               env = sus * (1.0f - (fi - ads) * idr);

        float nz = sh_noise[b * 256 + tid];               // LDS, conflict-free
        float nn = fmaf(nz, 2.0f, -1.0f) * nl;
        float sig = ((acc[b] + nn) * env) * gn;
        if (!act) sig = 0.0f;
        if (act) out[b * T_LEN + i] = sig;

        unsigned int mu = __reduce_max_sync(0xFFFFFFFFu,
                                            __float_as_uint(fabsf(sig)));
        if ((tid & 31) == 0) atomicMax(&sh_max[b], mu);
    }
    __syncthreads();
    // plain stores — [batch][block] slots, overwritten every call
    if (tid < NBATCH)
        g_partial[tid * MAIN_NB + blockIdx.x] = __uint_as_float(sh_max[tid]);
}

// ---------------------------------------------------------------------------
// Norm kernel: block (x, b) redundantly reduces batch b's 690 contiguous
// partials (L2-resident, coalesced), then scales its 2-float4 chunk of row b.
// No atomics, no inter-block sync, nothing to reset.
// ---------------------------------------------------------------------------
__global__ void __launch_bounds__(256) ddsp_norm(float4* __restrict__ out) {
    __shared__ float sh_wmax[8];
    __shared__ float sh_inv;
    const int T4 = T_LEN / 4;                 // 44100 float4 per row
    int b = blockIdx.y;
    int tid = threadIdx.x;

    const float* part = g_partial + b * MAIN_NB;
    float m = 0.0f;
    for (int j = tid; j < MAIN_NB; j += 256)
        m = fmaxf(m, part[j]);
    unsigned int mu = __reduce_max_sync(0xFFFFFFFFu, __float_as_uint(m));
    if ((tid & 31) == 0) sh_wmax[tid >> 5] = __uint_as_float(mu);
    __syncthreads();
    if (tid == 0) {
        float mm = sh_wmax[0];
#pragma unroll
        for (int w = 1; w < 8; w++) mm = fmaxf(mm, sh_wmax[w]);
        sh_inv = 1.0f / (mm + 1e-5f);
    }
    __syncthreads();
    float inv = sh_inv;

    float4* row = out + (size_t)b * T4;
    int i0 = blockIdx.x * 512 + tid;
    int i1 = i0 + 256;
    bool a0 = (i0 < T4), a1 = (i1 < T4);
    float4 v0, v1;
    if (a0) v0 = row[i0];
    if (a1) v1 = row[i1];
    if (a0) {
        v0.x *= inv; v0.y *= inv; v0.z *= inv; v0.w *= inv;
        row[i0] = v0;
    }
    if (a1) {
        v1.x *= inv; v1.y *= inv; v1.z *= inv; v1.w *= inv;
        row[i1] = v1;
    }
}

extern "C" void kernel_launch(void* const* d_in, const int* in_sizes, int n_in,
                              void* d_out, int out_size) {
    // input order: base_audio, harmonic_dist, noise_bands, adsr, gain, noise
    const float* hd     = (const float*)d_in[1];
    const float* nbands = (const float*)d_in[2];
    const float* adsr   = (const float*)d_in[3];
    const float* gain   = (const float*)d_in[4];
    const float* noise  = (const float*)d_in[5];
    float* out = (float*)d_out;

    ddsp_main<<<MAIN_NB, 256>>>(hd, nbands, adsr, gain, noise, out);
    ddsp_norm<<<dim3(NORM_BPR, NBATCH), 256>>>((float4*)out);
}

// round 16
// speedup vs baseline: 1.0650x; 1.0650x over previous
#include <cuda_runtime.h>
#include <math.h>

#define T_LEN    176400
#define NBATCH   16
#define NBH      8            // batches per thread (half)
#define NHARM    64
#define NBANDS   65
#define MAIN_NB  690          // ceil(176400/256); grid = (690, 2)
#define NORM_BPR 87           // 87*512 = 44544 >= 44100 float4 per row
#define PI_D 3.141592653589793115997963468544185161590576171875

// Scratch (no allocations allowed). Layout [batch][block]: norm's reduce
// reads are coalesced. Every slot overwritten by plain stores each call
// before being read -> no reset needed, replay-deterministic.
__device__ float g_partial[NBATCH * MAIN_NB];

// ---------------------------------------------------------------------------
// Range reduction, bit-exact w.r.t. the reference's f32 argument:
//  n = RNE(arg/2pi) via 1.5*2^23 magic; 2-term Cody-Waite -> r in [-pi,pi]
//  (4 fma-pipe ops), then __sinf(r) on the MUFU pipe (verified 2.6e-7).
// ---------------------------------------------------------------------------
__device__ __forceinline__ float sin_reduced(float a) {
    const float I2PI  = 0.15915494309189535f;
    const float MAGIC = 12582912.0f;                // 1.5 * 2^23
    const float C1    = 6.28318548202514648437500f; // fl32(2*pi)
    const float C2N   = 1.7484556000744625e-7f;     // -(2*pi - C1)
    float t  = fmaf(a, I2PI, MAGIC);
    float nf = t - MAGIC;                           // RNE(a/2pi), exact int
    float r  = fmaf(nf, -C1, a);
    r = fmaf(nf, C2N, r);                           // r in ~[-pi, pi]
    return __sinf(r);                               // MUFU pipe
}

// ---------------------------------------------------------------------------
// Main kernel: one thread = one time sample x 8 batches (blockIdx.y = half).
// R16 = R14 (best config: 31.5us) + warp-parallel prologue:
//  - warp j reduces batch j's 65 noise bands (32 lanes + 5-shfl butterfly)
//    replacing the single-thread 65-load serial chain that stalled all 8
//    warps of every block before the first barrier
//  - noise values prefetched into regs BEFORE the mainloop (R14-validated)
//  - per-batch max via REDUX.MAX (R14-validated)
// ---------------------------------------------------------------------------
__global__ void ddsp_main(
    const float* __restrict__ hd,      // (16, 64)
    const float* __restrict__ nbands,  // (16, 65)
    const float* __restrict__ adsr,    // (16, 4)
    const float* __restrict__ gain,    // (16, 1)
    const float* __restrict__ noise,   // (16, T)
    float* __restrict__ out)           // (16, T)
{
    __shared__ __align__(16) float sh_hd[NHARM * NBH];  // [k][j] for this half
    __shared__ float sh_ck[NHARM];
    __shared__ float sh_par[NBH * 12];
    __shared__ unsigned int sh_max[NBH];

    int tid = threadIdx.x;
    int bh  = blockIdx.y;              // 0 or 1: batches bh*8 .. bh*8+7

    for (int idx = tid; idx < NHARM * NBH; idx += 256) {
        int k = idx >> 3, j = idx & 7;
        sh_hd[idx] = hd[(bh * NBH + j) * NHARM + k];
    }
    if (tid < NHARM) {
        const float C32 = (float)(2.0 * PI_D * 440.0);   // fl32(2*pi*440)
        sh_ck[tid] = __fmul_rn(C32, (float)(tid + 1));   // bit-exact ref ck
    }
    // warp-parallel per-batch prologue: warp w handles batch bh*8+w
    {
        int w = tid >> 5, l = tid & 31;
        int b = bh * NBH + w;
        float ps = 0.0f;
        for (int j = l; j < NBANDS; j += 32) ps += nbands[b * NBANDS + j];
#pragma unroll
        for (int off = 16; off; off >>= 1)
            ps += __shfl_xor_sync(0xFFFFFFFFu, ps, off);
        if (l == 0) {
            sh_max[w] = 0u;
            float nl = (ps / (float)NBANDS) * 0.1f;

            float attack  = adsr[b * 4 + 0];
            float decay   = adsr[b * 4 + 1];
            float sus     = adsr[b * 4 + 2];
            float release = adsr[b * 4 + 3];

            int a  = (int)floorf(__fmul_rn(__fmul_rn(attack,  0.5f), 44100.0f)) + 1;
            int dd = (int)floorf(__fmul_rn(__fmul_rn(decay,   0.5f), 44100.0f)) + 1;
            int rr = (int)floorf(__fmul_rn(__fmul_rn(release, 0.5f), 44100.0f)) + 1;
            int total = a + dd + rr;
            if (total > T_LEN) {
                float scale = __fdiv_rn((float)T_LEN, (float)total);
                a  = (int)floorf(__fmul_rn((float)a,  scale));
                dd = (int)floorf(__fmul_rn((float)dd, scale));
                rr = (int)floorf(__fmul_rn((float)rr, scale));
            }
            int ss = T_LEN - (a + dd + rr);
            if (ss < 0) ss = 0;

            float af = (float)a, df = (float)dd, sf = (float)ss, rf = (float)rr;
            float* P = sh_par + w * 12;
            P[0] = af;
            P[1] = af + df;
            P[2] = af + df + sf;
            P[3] = 1.0f / fmaxf(af - 1.0f, 1.0f);
            P[4] = 1.0f / fmaxf(df - 1.0f, 1.0f);
            P[5] = 1.0f / fmaxf(rf - 1.0f, 1.0f);
            P[6] = sus;
            P[7] = gain[b];
            P[8] = nl;
        }
    }
    __syncthreads();

    int i = blockIdx.x * 256 + tid;
    bool act = (i < T_LEN);
    float fi = (float)i;
    const float DELTA = 4.0f / 176399.0f;         // compile-time IEEE f32
    float ti = __fmul_rn(fi, DELTA);              // jax linspace: iota*delta

    // ---- noise prefetch: issue all 8 LDGs now; consumed after the mainloop
    float nz[NBH];
#pragma unroll
    for (int j = 0; j < NBH; j++) {
        int b = bh * NBH + j;
        nz[j] = act ? noise[b * T_LEN + i] : 0.0f;
    }

    float acc[NBH];
#pragma unroll
    for (int j = 0; j < NBH; j++) acc[j] = 0.0f;

#pragma unroll 8
    for (int k = 0; k < NHARM; k++) {
        float sv = sin_reduced(__fmul_rn(sh_ck[k], ti)); // ref f32 rounding
        const float4* hp = (const float4*)(sh_hd + k * NBH);
        float4 h0 = hp[0], h1 = hp[1];
        acc[0] = fmaf(h0.x, sv, acc[0]);  acc[1] = fmaf(h0.y, sv, acc[1]);
        acc[2] = fmaf(h0.z, sv, acc[2]);  acc[3] = fmaf(h0.w, sv, acc[3]);
        acc[4] = fmaf(h1.x, sv, acc[4]);  acc[5] = fmaf(h1.y, sv, acc[5]);
        acc[6] = fmaf(h1.z, sv, acc[6]);  acc[7] = fmaf(h1.w, sv, acc[7]);
    }

#pragma unroll
    for (int j = 0; j < NBH; j++) {
        int b = bh * NBH + j;
        const float* P = sh_par + j * 12;
        float af = P[0], afd = P[1], ads = P[2];
        float ida = P[3], idd = P[4], idr = P[5];
        float sus = P[6], gn = P[7], nl = P[8];

        float env;
        if (fi < af)       env = fi * ida;
        else if (fi < afd) env = 1.0f + ((sus - 1.0f) * (fi - af)) * idd;
        else if (fi < ads) env = sus;
        else               env = sus * (1.0f - (fi - ads) * idr);

        float nn = fmaf(nz[j], 2.0f, -1.0f) * nl;
        float sig = ((acc[j] + nn) * env) * gn;
        if (!act) sig = 0.0f;
        if (act) out[b * T_LEN + i] = sig;

        // one REDUX.MAX replaces the 5-shfl butterfly (nonneg -> uint order)
        unsigned int mu = __reduce_max_sync(0xFFFFFFFFu,
                                            __float_as_uint(fabsf(sig)));
        if ((tid & 31) == 0) atomicMax(&sh_max[j], mu);
    }
    __syncthreads();
    // plain stores — [batch][block] slots, overwritten every call
    if (tid < NBH)
        g_partial[(bh * NBH + tid) * MAIN_NB + blockIdx.x] =
            __uint_as_float(sh_max[tid]);
}

// ---------------------------------------------------------------------------
// Norm kernel: block (x, b) redundantly reduces batch b's 690 contiguous
// partials (L2-resident, coalesced), then scales its 2-float4 chunk of row b.
// No atomics, no inter-block sync, nothing to reset.
// ---------------------------------------------------------------------------
__global__ void __launch_bounds__(256) ddsp_norm(float4* __restrict__ out) {
    __shared__ float sh_wmax[8];
    __shared__ float sh_inv;
    const int T4 = T_LEN / 4;                 // 44100 float4 per row
    int b = blockIdx.y;
    int tid = threadIdx.x;

    const float* part = g_partial + b * MAIN_NB;
    float m = 0.0f;
    for (int j = tid; j < MAIN_NB; j += 256)
        m = fmaxf(m, part[j]);
    unsigned int mu = __reduce_max_sync(0xFFFFFFFFu, __float_as_uint(m));
    if ((tid & 31) == 0) sh_wmax[tid >> 5] = __uint_as_float(mu);
    __syncthreads();
    if (tid == 0) {
        float mm = sh_wmax[0];
#pragma unroll
        for (int w = 1; w < 8; w++) mm = fmaxf(mm, sh_wmax[w]);
        sh_inv = 1.0f / (mm + 1e-5f);
    }
    __syncthreads();
    float inv = sh_inv;

    float4* row = out + (size_t)b * T4;
    int i0 = blockIdx.x * 512 + tid;
    int i1 = i0 + 256;
    bool a0 = (i0 < T4), a1 = (i1 < T4);
    float4 v0, v1;
    if (a0) v0 = row[i0];
    if (a1) v1 = row[i1];
    if (a0) {
        v0.x *= inv; v0.y *= inv; v0.z *= inv; v0.w *= inv;
        row[i0] = v0;
    }
    if (a1) {
        v1.x *= inv; v1.y *= inv; v1.z *= inv; v1.w *= inv;
        row[i1] = v1;
    }
}

extern "C" void kernel_launch(void* const* d_in, const int* in_sizes, int n_in,
                              void* d_out, int out_size) {
    // input order: base_audio, harmonic_dist, noise_bands, adsr, gain, noise
    const float* hd     = (const float*)d_in[1];
    const float* nbands = (const float*)d_in[2];
    const float* adsr   = (const float*)d_in[3];
    const float* gain   = (const float*)d_in[4];
    const float* noise  = (const float*)d_in[5];
    float* out = (float*)d_out;

    ddsp_main<<<dim3(MAIN_NB, 2), 256>>>(hd, nbands, adsr, gain, noise, out);
    ddsp_norm<<<dim3(NORM_BPR, NBATCH), 256>>>((float4*)out);
}

// round 17
// speedup vs baseline: 1.0749x; 1.0092x over previous
#include <cuda_runtime.h>
#include <math.h>

#define T_LEN    176400
#define NBATCH   16
#define NBH      8            // batches per thread (half)
#define NHARM    64
#define NBANDS   65
#define MAIN_NB  690          // ceil(176400/256); grid = (690, 2)
#define NORM_BPR 87           // 87*512 = 44544 >= 44100 float4 per row
#define PI_D 3.141592653589793115997963468544185161590576171875

// Scratch (no allocations allowed). Layout [batch][block]: norm's reduce
// reads are coalesced. Every slot overwritten by plain stores each call
// before being read -> no reset needed, replay-deterministic.
__device__ float g_partial[NBATCH * MAIN_NB];

// ---------------------------------------------------------------------------
// Range reduction, bit-exact w.r.t. the reference's f32 argument:
//  n = RNE(arg/2pi) via 1.5*2^23 magic; 2-term Cody-Waite -> r in [-pi,pi]
//  (4 fma-pipe ops), then __sinf(r) on the MUFU pipe (verified 2.6e-7).
// ---------------------------------------------------------------------------
__device__ __forceinline__ float sin_reduced(float a) {
    const float I2PI  = 0.15915494309189535f;
    const float MAGIC = 12582912.0f;                // 1.5 * 2^23
    const float C1    = 6.28318548202514648437500f; // fl32(2*pi)
    const float C2N   = 1.7484556000744625e-7f;     // -(2*pi - C1)
    float t  = fmaf(a, I2PI, MAGIC);
    float nf = t - MAGIC;                           // RNE(a/2pi), exact int
    float r  = fmaf(nf, -C1, a);
    r = fmaf(nf, C2N, r);                           // r in ~[-pi, pi]
    return __sinf(r);                               // MUFU pipe
}

// ---------------------------------------------------------------------------
// Main kernel: one thread = one time sample x 8 batches (blockIdx.y = half).
// = R16 (best: 31.5us) + coalesced sh_hd load + PDL completion trigger so
// the norm kernel's launch overlaps this kernel's drain.
// ---------------------------------------------------------------------------
__global__ void ddsp_main(
    const float* __restrict__ hd,      // (16, 64)
    const float* __restrict__ nbands,  // (16, 65)
    const float* __restrict__ adsr,    // (16, 4)
    const float* __restrict__ gain,    // (16, 1)
    const float* __restrict__ noise,   // (16, T)
    float* __restrict__ out)           // (16, T)
{
    __shared__ __align__(16) float sh_hd[NHARM * NBH];  // [k][j] for this half
    __shared__ float sh_ck[NHARM];
    __shared__ float sh_par[NBH * 12];
    __shared__ unsigned int sh_max[NBH];

    int tid = threadIdx.x;
    int bh  = blockIdx.y;              // 0 or 1: batches bh*8 .. bh*8+7

    // coalesced: linear LDG from hd + transposed STS into [k][j]
    for (int idx = tid; idx < NHARM * NBH; idx += 256) {
        float v = hd[bh * (NBH * NHARM) + idx];   // contiguous
        int j = idx >> 6, k = idx & 63;           // idx = j*64 + k
        sh_hd[k * NBH + j] = v;
    }
    if (tid < NHARM) {
        const float C32 = (float)(2.0 * PI_D * 440.0);   // fl32(2*pi*440)
        sh_ck[tid] = __fmul_rn(C32, (float)(tid + 1));   // bit-exact ref ck
    }
    // warp-parallel per-batch prologue: warp w handles batch bh*8+w
    {
        int w = tid >> 5, l = tid & 31;
        int b = bh * NBH + w;
        float ps = 0.0f;
        for (int j = l; j < NBANDS; j += 32) ps += nbands[b * NBANDS + j];
#pragma unroll
        for (int off = 16; off; off >>= 1)
            ps += __shfl_xor_sync(0xFFFFFFFFu, ps, off);
        if (l == 0) {
            sh_max[w] = 0u;
            float nl = (ps / (float)NBANDS) * 0.1f;

            float attack  = adsr[b * 4 + 0];
            float decay   = adsr[b * 4 + 1];
            float sus     = adsr[b * 4 + 2];
            float release = adsr[b * 4 + 3];

            int a  = (int)floorf(__fmul_rn(__fmul_rn(attack,  0.5f), 44100.0f)) + 1;
            int dd = (int)floorf(__fmul_rn(__fmul_rn(decay,   0.5f), 44100.0f)) + 1;
            int rr = (int)floorf(__fmul_rn(__fmul_rn(release, 0.5f), 44100.0f)) + 1;
            int total = a + dd + rr;
            if (total > T_LEN) {
                float scale = __fdiv_rn((float)T_LEN, (float)total);
                a  = (int)floorf(__fmul_rn((float)a,  scale));
                dd = (int)floorf(__fmul_rn((float)dd, scale));
                rr = (int)floorf(__fmul_rn((float)rr, scale));
            }
            int ss = T_LEN - (a + dd + rr);
            if (ss < 0) ss = 0;

            float af = (float)a, df = (float)dd, sf = (float)ss, rf = (float)rr;
            float* P = sh_par + w * 12;
            P[0] = af;
            P[1] = af + df;
            P[2] = af + df + sf;
            P[3] = 1.0f / fmaxf(af - 1.0f, 1.0f);
            P[4] = 1.0f / fmaxf(df - 1.0f, 1.0f);
            P[5] = 1.0f / fmaxf(rf - 1.0f, 1.0f);
            P[6] = sus;
            P[7] = gain[b];
            P[8] = nl;
        }
    }
    __syncthreads();

    int i = blockIdx.x * 256 + tid;
    bool act = (i < T_LEN);
    float fi = (float)i;
    const float DELTA = 4.0f / 176399.0f;         // compile-time IEEE f32
    float ti = __fmul_rn(fi, DELTA);              // jax linspace: iota*delta

    // ---- noise prefetch: issue all 8 LDGs now; consumed after the mainloop
    float nz[NBH];
#pragma unroll
    for (int j = 0; j < NBH; j++) {
        int b = bh * NBH + j;
        nz[j] = act ? noise[b * T_LEN + i] : 0.0f;
    }

    float acc[NBH];
#pragma unroll
    for (int j = 0; j < NBH; j++) acc[j] = 0.0f;

#pragma unroll 8
    for (int k = 0; k < NHARM; k++) {
        float sv = sin_reduced(__fmul_rn(sh_ck[k], ti)); // ref f32 rounding
        const float4* hp = (const float4*)(sh_hd + k * NBH);
        float4 h0 = hp[0], h1 = hp[1];
        acc[0] = fmaf(h0.x, sv, acc[0]);  acc[1] = fmaf(h0.y, sv, acc[1]);
        acc[2] = fmaf(h0.z, sv, acc[2]);  acc[3] = fmaf(h0.w, sv, acc[3]);
        acc[4] = fmaf(h1.x, sv, acc[4]);  acc[5] = fmaf(h1.y, sv, acc[5]);
        acc[6] = fmaf(h1.z, sv, acc[6]);  acc[7] = fmaf(h1.w, sv, acc[7]);
    }

#pragma unroll
    for (int j = 0; j < NBH; j++) {
        int b = bh * NBH + j;
        const float* P = sh_par + j * 12;
        float af = P[0], afd = P[1], ads = P[2];
        float ida = P[3], idd = P[4], idr = P[5];
        float sus = P[6], gn = P[7], nl = P[8];

        float env;
        if (fi < af)       env = fi * ida;
        else if (fi < afd) env = 1.0f + ((sus - 1.0f) * (fi - af)) * idd;
        else if (fi < ads) env = sus;
        else               env = sus * (1.0f - (fi - ads) * idr);

        float nn = fmaf(nz[j], 2.0f, -1.0f) * nl;
        float sig = ((acc[j] + nn) * env) * gn;
        if (!act) sig = 0.0f;
        if (act) out[b * T_LEN + i] = sig;

        unsigned int mu = __reduce_max_sync(0xFFFFFFFFu,
                                            __float_as_uint(fabsf(sig)));
        if ((tid & 31) == 0) atomicMax(&sh_max[j], mu);
    }
    __syncthreads();
    // plain stores — [batch][block] slots, overwritten every call
    if (tid < NBH) {
        g_partial[(bh * NBH + tid) * MAIN_NB + blockIdx.x] =
            __uint_as_float(sh_max[tid]);
        __threadfence();                 // flush before PDL trigger
    }
    __syncthreads();
    cudaTriggerProgrammaticLaunchCompletion();   // let norm's grid launch now
}

// ---------------------------------------------------------------------------
// Norm kernel (PDL secondary): waits on the programmatic dependency, then
// block (x, b) redundantly reduces batch b's 690 contiguous partials and
// scales its 2-float4 chunk of row b. No atomics, nothing to reset.
// ---------------------------------------------------------------------------
__global__ void __launch_bounds__(256) ddsp_norm(float4* __restrict__ out) {
    __shared__ float sh_wmax[8];
    __shared__ float sh_inv;
    const int T4 = T_LEN / 4;                 // 44100 float4 per row
    int b = blockIdx.y;
    int tid = threadIdx.x;

    cudaGridDependencySynchronize();   // all ddsp_main writes now visible

    const float* part = g_partial + b * MAIN_NB;
    float m = 0.0f;
    for (int j = tid; j < MAIN_NB; j += 256)
        m = fmaxf(m, part[j]);
    unsigned int mu = __reduce_max_sync(0xFFFFFFFFu, __float_as_uint(m));
    if ((tid & 31) == 0) sh_wmax[tid >> 5] = __uint_as_float(mu);
    __syncthreads();
    if (tid == 0) {
        float mm = sh_wmax[0];
#pragma unroll
        for (int w = 1; w < 8; w++) mm = fmaxf(mm, sh_wmax[w]);
        sh_inv = 1.0f / (mm + 1e-5f);
    }
    __syncthreads();
    float inv = sh_inv;

    float4* row = out + (size_t)b * T4;
    int i0 = blockIdx.x * 512 + tid;
    int i1 = i0 + 256;
    bool a0 = (i0 < T4), a1 = (i1 < T4);
    float4 v0, v1;
    if (a0) v0 = row[i0];
    if (a1) v1 = row[i1];
    if (a0) {
        v0.x *= inv; v0.y *= inv; v0.z *= inv; v0.w *= inv;
        row[i0] = v0;
    }
    if (a1) {
        v1.x *= inv; v1.y *= inv; v1.z *= inv; v1.w *= inv;
        row[i1] = v1;
    }
}

extern "C" void kernel_launch(void* const* d_in, const int* in_sizes, int n_in,
                              void* d_out, int out_size) {
    // input order: base_audio, harmonic_dist, noise_bands, adsr, gain, noise
    const float* hd     = (const float*)d_in[1];
    const float* nbands = (const float*)d_in[2];
    const float* adsr   = (const float*)d_in[3];
    const float* gain   = (const float*)d_in[4];
    const float* noise  = (const float*)d_in[5];
    float* out = (float*)d_out;

    ddsp_main<<<dim3(MAIN_NB, 2), 256>>>(hd, nbands, adsr, gain, noise, out);

    // norm launched as a PDL secondary: its grid setup overlaps main's drain
    cudaLaunchConfig_t cfg = {};
    cfg.gridDim  = dim3(NORM_BPR, NBATCH, 1);
    cfg.blockDim = dim3(256, 1, 1);
    cudaLaunchAttribute attrs[1];
    attrs[0].id = cudaLaunchAttributeProgrammaticStreamSerialization;
    attrs[0].val.programmaticStreamSerializationAllowed = 1;
    cfg.attrs = attrs;
    cfg.numAttrs = 1;
    cudaLaunchKernelEx(&cfg, ddsp_norm, (float4*)out);
}